// round 12
// baseline (speedup 1.0000x reference)
#include <cuda_runtime.h>
#include <cuda_bf16.h>

// D_MODEL = 2048, QUAT_DIM = 512, B*T = 16384
// Inputs: x [B,T,2048] f32, q_left [4,512] f32, q_right [4,512] f32, gate [512] f32
// Output: [B,T,2048] f32
//
// gate broadcasts uniformly over the FFT axis => ifft(fft(x)*g).real == g*x.
// Both Hamilton products are linear in x => fused per-feature 4x4 matrix M[d].
//
// R10: R9 persistent stream + strength-reduced addressing: running pointers
// with constant stride, prefetch via constant immediate offset (7.27MB < 8MB
// LDG immediate range). Cuts per-iteration integer ops ~5x.

#define QD 512
#define NBT (4 * 4096)       // 16384 rows
#define THREADS 256
#define NBLK 444             // 148 SMs x 3 resident
#define STRIDE (NBLK * 2048) // floats advanced per iteration

__device__ __forceinline__ float2 f2_fma(float2 a, float2 b, float2 c) {
    return make_float2(fmaf(a.x, b.x, c.x), fmaf(a.y, b.y, c.y));
}
__device__ __forceinline__ float2 f2_mul(float2 a, float2 b) {
    return make_float2(a.x * b.x, a.y * b.y);
}

__global__ void __launch_bounds__(THREADS)
evolve_persist_kernel(const float* __restrict__ x,
                      const float* __restrict__ ql,
                      const float* __restrict__ qr,
                      const float* __restrict__ gate,
                      float* __restrict__ out) {
    const int d2 = threadIdx.x * 2;        // feature pair
    const int bid = blockIdx.x;

    // ---- Build fused 4x4 matrices for 2 features (elementwise float2) ----
    float2 lv[4], rv[4];
#pragma unroll
    for (int i = 0; i < 4; i++) {
        lv[i] = *reinterpret_cast<const float2*>(ql + i * QD + d2);
        rv[i] = *reinterpret_cast<const float2*>(qr + i * QD + d2);
    }
    {   // normalize l
        float2 s = make_float2(1e-8f, 1e-8f);
#pragma unroll
        for (int i = 0; i < 4; i++) s = f2_fma(lv[i], lv[i], s);
        float2 inv = make_float2(rsqrtf(s.x), rsqrtf(s.y));
#pragma unroll
        for (int i = 0; i < 4; i++) lv[i] = f2_mul(lv[i], inv);
    }
    {   // normalize r + conjugate
        float2 s = make_float2(1e-8f, 1e-8f);
#pragma unroll
        for (int i = 0; i < 4; i++) s = f2_fma(rv[i], rv[i], s);
        float2 inv = make_float2(rsqrtf(s.x), rsqrtf(s.y));
        rv[0] = f2_mul(rv[0], inv);
        float2 ninv = make_float2(-inv.x, -inv.y);
#pragma unroll
        for (int i = 1; i < 4; i++) rv[i] = f2_mul(rv[i], ninv);
    }

    // Hamilton structure (constant-folded): L[r][k]=sL*l[p[r][k]], R[k][c]=sR*r[p[k][c]]
    const int   pP[4][4] = {{0,1,2,3},{1,0,3,2},{2,3,0,1},{3,2,1,0}};
    const float sL[4][4] = {{1,-1,-1,-1},{1,1,-1,1},{1,1,1,-1},{1,-1,1,1}};
    const float sR[4][4] = {{1,-1,-1,-1},{1,1,1,-1},{1,-1,1,1},{1,1,-1,1}};

    float2 g2 = *reinterpret_cast<const float2*>(gate + d2);

    float2 M[16];
#pragma unroll
    for (int r = 0; r < 4; r++) {
#pragma unroll
        for (int c = 0; c < 4; c++) {
            float2 acc = make_float2(0.f, 0.f);
#pragma unroll
            for (int k = 0; k < 4; k++) {
                float2 t = f2_mul(lv[pP[r][k]], rv[pP[k][c]]);
                if (sL[r][k] * sR[k][c] > 0.f) { acc.x += t.x; acc.y += t.y; }
                else                           { acc.x -= t.x; acc.y -= t.y; }
            }
            M[r * 4 + c] = f2_mul(acc, g2);
        }
    }

    // ---- Persistent row loop: running pointers, constant-stride prefetch ----
    const float* xc = x + (size_t)bid * 2048 + d2;
    float* oc = out + (size_t)bid * 2048 + d2;

    float2 buf[2][4];
#pragma unroll
    for (int c = 0; c < 4; c++)
        buf[0][c] = __ldcs(reinterpret_cast<const float2*>(xc + c * QD));
    if (bid + NBLK < NBT) {
#pragma unroll
        for (int c = 0; c < 4; c++)
            buf[1][c] = __ldcs(reinterpret_cast<const float2*>(xc + STRIDE + c * QD));
    }

    int par = 0;
#pragma unroll 2
    for (int row = bid; row < NBT; row += NBLK) {
        float2 in[4];
#pragma unroll
        for (int c = 0; c < 4; c++) in[c] = buf[par][c];

        if (row + 2 * NBLK < NBT) {
#pragma unroll
            for (int c = 0; c < 4; c++)
                buf[par][c] = __ldcs(reinterpret_cast<const float2*>(
                    xc + 2 * STRIDE + c * QD));
        }

#pragma unroll
        for (int r = 0; r < 4; r++) {
            float2 a = f2_mul(M[r * 4 + 0], in[0]);
            a = f2_fma(M[r * 4 + 1], in[1], a);
            a = f2_fma(M[r * 4 + 2], in[2], a);
            a = f2_fma(M[r * 4 + 3], in[3], a);
            __stcs(reinterpret_cast<float2*>(oc + r * QD), a);
        }

        xc += STRIDE;
        oc += STRIDE;
        par ^= 1;
    }
}

extern "C" void kernel_launch(void* const* d_in, const int* in_sizes, int n_in,
                              void* d_out, int out_size) {
    const float* x    = (const float*)d_in[0];
    const float* ql   = (const float*)d_in[1];
    const float* qr   = (const float*)d_in[2];
    const float* gate = (const float*)d_in[3];
    float* out = (float*)d_out;

    evolve_persist_kernel<<<NBLK, THREADS>>>(x, ql, qr, gate, out);
}

// round 13
// speedup vs baseline: 1.0190x; 1.0190x over previous
#include <cuda_runtime.h>
#include <cuda_bf16.h>

// D_MODEL = 2048, QUAT_DIM = 512, B*T = 16384
// Inputs: x [B,T,2048] f32, q_left [4,512] f32, q_right [4,512] f32, gate [512] f32
// Output: [B,T,2048] f32
//
// gate broadcasts uniformly over the FFT axis => ifft(fft(x)*g).real == g*x.
// Both Hamilton products are linear in x => fused per-feature 4x4 matrix M[d].
//
// R12: persistent grid (444 = 148 SMs x 3 resident), two rows per iteration:
// 8 front-batched streaming loads -> compute -> 8 grouped streaming stores.
// Longer same-direction DRAM bursts, half the loop overhead per byte, no
// double-buffer bookkeeping.

#define QD 512
#define NBT (4 * 4096)        // 16384 rows
#define THREADS 256
#define NBLK 444              // 148 SMs x 3 resident
#define STRIDE (NBLK * 2048)  // floats between a block's consecutive rows

__device__ __forceinline__ float2 f2_fma(float2 a, float2 b, float2 c) {
    return make_float2(fmaf(a.x, b.x, c.x), fmaf(a.y, b.y, c.y));
}
__device__ __forceinline__ float2 f2_mul(float2 a, float2 b) {
    return make_float2(a.x * b.x, a.y * b.y);
}

__global__ void __launch_bounds__(THREADS)
evolve_pair_kernel(const float* __restrict__ x,
                   const float* __restrict__ ql,
                   const float* __restrict__ qr,
                   const float* __restrict__ gate,
                   float* __restrict__ out) {
    const int d2 = threadIdx.x * 2;        // feature pair
    const int bid = blockIdx.x;

    // ---- Build fused 4x4 matrices for 2 features (elementwise float2) ----
    float2 lv[4], rv[4];
#pragma unroll
    for (int i = 0; i < 4; i++) {
        lv[i] = *reinterpret_cast<const float2*>(ql + i * QD + d2);
        rv[i] = *reinterpret_cast<const float2*>(qr + i * QD + d2);
    }
    {   // normalize l
        float2 s = make_float2(1e-8f, 1e-8f);
#pragma unroll
        for (int i = 0; i < 4; i++) s = f2_fma(lv[i], lv[i], s);
        float2 inv = make_float2(rsqrtf(s.x), rsqrtf(s.y));
#pragma unroll
        for (int i = 0; i < 4; i++) lv[i] = f2_mul(lv[i], inv);
    }
    {   // normalize r + conjugate
        float2 s = make_float2(1e-8f, 1e-8f);
#pragma unroll
        for (int i = 0; i < 4; i++) s = f2_fma(rv[i], rv[i], s);
        float2 inv = make_float2(rsqrtf(s.x), rsqrtf(s.y));
        rv[0] = f2_mul(rv[0], inv);
        float2 ninv = make_float2(-inv.x, -inv.y);
#pragma unroll
        for (int i = 1; i < 4; i++) rv[i] = f2_mul(rv[i], ninv);
    }

    // Hamilton structure (constant-folded): L[r][k]=sL*l[p[r][k]], R[k][c]=sR*r[p[k][c]]
    const int   pP[4][4] = {{0,1,2,3},{1,0,3,2},{2,3,0,1},{3,2,1,0}};
    const float sL[4][4] = {{1,-1,-1,-1},{1,1,-1,1},{1,1,1,-1},{1,-1,1,1}};
    const float sR[4][4] = {{1,-1,-1,-1},{1,1,1,-1},{1,-1,1,1},{1,1,-1,1}};

    float2 g2 = *reinterpret_cast<const float2*>(gate + d2);

    float2 M[16];
#pragma unroll
    for (int r = 0; r < 4; r++) {
#pragma unroll
        for (int c = 0; c < 4; c++) {
            float2 acc = make_float2(0.f, 0.f);
#pragma unroll
            for (int k = 0; k < 4; k++) {
                float2 t = f2_mul(lv[pP[r][k]], rv[pP[k][c]]);
                if (sL[r][k] * sR[k][c] > 0.f) { acc.x += t.x; acc.y += t.y; }
                else                           { acc.x -= t.x; acc.y -= t.y; }
            }
            M[r * 4 + c] = f2_mul(acc, g2);
        }
    }

    // ---- Persistent loop: two rows per iteration (row, row+NBLK) ----
    const float* xc = x + (size_t)bid * 2048 + d2;
    float* oc = out + (size_t)bid * 2048 + d2;
    int row = bid;

    while (row + NBLK < NBT) {
        // 8 front-batched streaming loads (two rows)
        float2 in0[4], in1[4];
#pragma unroll
        for (int c = 0; c < 4; c++)
            in0[c] = __ldcs(reinterpret_cast<const float2*>(xc + c * QD));
#pragma unroll
        for (int c = 0; c < 4; c++)
            in1[c] = __ldcs(reinterpret_cast<const float2*>(xc + STRIDE + c * QD));

        float2 o0[4], o1[4];
#pragma unroll
        for (int r = 0; r < 4; r++) {
            float2 a = f2_mul(M[r * 4 + 0], in0[0]);
            a = f2_fma(M[r * 4 + 1], in0[1], a);
            a = f2_fma(M[r * 4 + 2], in0[2], a);
            a = f2_fma(M[r * 4 + 3], in0[3], a);
            o0[r] = a;
            float2 b = f2_mul(M[r * 4 + 0], in1[0]);
            b = f2_fma(M[r * 4 + 1], in1[1], b);
            b = f2_fma(M[r * 4 + 2], in1[2], b);
            b = f2_fma(M[r * 4 + 3], in1[3], b);
            o1[r] = b;
        }

        // 8 grouped streaming stores
#pragma unroll
        for (int r = 0; r < 4; r++)
            __stcs(reinterpret_cast<float2*>(oc + r * QD), o0[r]);
#pragma unroll
        for (int r = 0; r < 4; r++)
            __stcs(reinterpret_cast<float2*>(oc + STRIDE + r * QD), o1[r]);

        xc += 2 * STRIDE;
        oc += 2 * STRIDE;
        row += 2 * NBLK;
    }

    // Tail: at most one leftover row
    if (row < NBT) {
        float2 in[4];
#pragma unroll
        for (int c = 0; c < 4; c++)
            in[c] = __ldcs(reinterpret_cast<const float2*>(xc + c * QD));
#pragma unroll
        for (int r = 0; r < 4; r++) {
            float2 a = f2_mul(M[r * 4 + 0], in[0]);
            a = f2_fma(M[r * 4 + 1], in[1], a);
            a = f2_fma(M[r * 4 + 2], in[2], a);
            a = f2_fma(M[r * 4 + 3], in[3], a);
            __stcs(reinterpret_cast<float2*>(oc + r * QD), a);
        }
    }
}

extern "C" void kernel_launch(void* const* d_in, const int* in_sizes, int n_in,
                              void* d_out, int out_size) {
    const float* x    = (const float*)d_in[0];
    const float* ql   = (const float*)d_in[1];
    const float* qr   = (const float*)d_in[2];
    const float* gate = (const float*)d_in[3];
    float* out = (float*)d_out;

    evolve_pair_kernel<<<NBLK, THREADS>>>(x, ql, qr, gate, out);
}